// round 1
// baseline (speedup 1.0000x reference)
#include <cuda_runtime.h>

// Problem constants
#define BB   16
#define SS   577
#define DD   1408
#define HH   16
#define HD   88
#define SCALE_F 0.10660035817780521f  // 1/sqrt(88)

// Scratch (device globals: allocation-free per harness rules)
__device__ float g_qkv[(size_t)BB * SS * 3 * DD];   // [B,S,3D]  (~156 MB)
__device__ float g_att[(size_t)BB * SS * DD];       // [B,S,D]   (~52 MB)

// ---------------------------------------------------------------------------
// SGEMM + bias:  C[M,N] = A[M,K] @ B[K,N] + bias[N]
// 128x128 block tile, BK=8, 256 threads, 8x8 micro-tile per thread.
// N and K are multiples of 128 / 8 respectively for both calls; only M has a
// tail (9232 = 72*128 + 16).
// ---------------------------------------------------------------------------
__global__ __launch_bounds__(256) void sgemm_bias_kernel(
    const float* __restrict__ A, const float* __restrict__ Bm,
    const float* __restrict__ bias, float* __restrict__ C,
    int M, int N, int K)
{
    __shared__ float As[8][128];   // As[k][m]
    __shared__ float Bs[8][128];   // Bs[k][n]

    const int m0 = blockIdx.y * 128;
    const int n0 = blockIdx.x * 128;
    const int tid = threadIdx.x;

    // global-load mapping
    const int arow = tid >> 1;          // 0..127
    const int acol = (tid & 1) * 4;     // 0 or 4
    const int brow = tid >> 5;          // 0..7
    const int bcol = (tid & 31) * 4;    // 0..124

    // compute mapping
    const int tx = tid & 15;            // n-group
    const int ty = tid >> 4;            // m-group

    const bool avalid = (m0 + arow) < M;
    const float* Aptr = A + (size_t)(m0 + arow) * K + acol;
    const float* Bptr = Bm + (size_t)brow * N + n0 + bcol;

    float acc[8][8];
#pragma unroll
    for (int i = 0; i < 8; i++)
#pragma unroll
        for (int j = 0; j < 8; j++) acc[i][j] = 0.f;

    for (int k0 = 0; k0 < K; k0 += 8) {
        float4 av = avalid ? *(const float4*)Aptr : make_float4(0.f, 0.f, 0.f, 0.f);
        float4 bv = *(const float4*)Bptr;

        As[acol + 0][arow] = av.x;
        As[acol + 1][arow] = av.y;
        As[acol + 2][arow] = av.z;
        As[acol + 3][arow] = av.w;
        *(float4*)&Bs[brow][bcol] = bv;
        __syncthreads();

#pragma unroll
        for (int k = 0; k < 8; k++) {
            float4 a0 = *(const float4*)&As[k][ty * 8];
            float4 a1 = *(const float4*)&As[k][ty * 8 + 4];
            float4 b0 = *(const float4*)&Bs[k][tx * 8];
            float4 b1 = *(const float4*)&Bs[k][tx * 8 + 4];
            float a[8] = {a0.x, a0.y, a0.z, a0.w, a1.x, a1.y, a1.z, a1.w};
            float b[8] = {b0.x, b0.y, b0.z, b0.w, b1.x, b1.y, b1.z, b1.w};
#pragma unroll
            for (int i = 0; i < 8; i++)
#pragma unroll
                for (int j = 0; j < 8; j++)
                    acc[i][j] = fmaf(a[i], b[j], acc[i][j]);
        }
        __syncthreads();

        Aptr += 8;
        Bptr += (size_t)8 * N;
    }

    // epilogue: add bias, vectorized stores
#pragma unroll
    for (int i = 0; i < 8; i++) {
        int row = m0 + ty * 8 + i;
        if (row >= M) continue;
        int col = n0 + tx * 8;
        float4 o0, o1;
        o0.x = acc[i][0] + bias[col + 0];
        o0.y = acc[i][1] + bias[col + 1];
        o0.z = acc[i][2] + bias[col + 2];
        o0.w = acc[i][3] + bias[col + 3];
        o1.x = acc[i][4] + bias[col + 4];
        o1.y = acc[i][5] + bias[col + 5];
        o1.z = acc[i][6] + bias[col + 6];
        o1.w = acc[i][7] + bias[col + 7];
        *(float4*)&C[(size_t)row * N + col] = o0;
        *(float4*)&C[(size_t)row * N + col + 4] = o1;
    }
}

// ---------------------------------------------------------------------------
// Flash-style attention. One CTA = (batch b, head h, 64-query tile).
// 256 threads = 16 query-groups (qg, 4 queries each) x 16 lanes (kg).
//  - QK^T: thread (qg,kg) computes 4x4 scores via float4 LDS of transposed Q/K.
//  - online softmax with shfl reductions across the 16 kg lanes.
//  - P stored transposed to smem; PV: kg acts as a 6-wide dim group.
// smem: sQt[88][64] | sKt[88][64] | sV[64][96] | sPt[64][68]  = 87,040 B
// ---------------------------------------------------------------------------
__global__ __launch_bounds__(256) void attn_kernel(
    const float* __restrict__ qkv, float* __restrict__ out)
{
    extern __shared__ float sm[];
    float* sQ = sm;                          // [88][64]  sQ[d*64+q] (pre-scaled)
    float* sK = sm + 88 * 64;                // [88][64]  sK[d*64+k]
    float* sV = sm + 2 * 88 * 64;            // [64][96]  sV[k*96+d]
    float* sP = sm + 2 * 88 * 64 + 64 * 96;  // [64][68]  sP[k*68+q]

    const int b = blockIdx.z;
    const int h = blockIdx.y;
    const int q0 = blockIdx.x * 64;
    const int tid = threadIdx.x;
    const int qg = tid >> 4;   // 0..15
    const int kg = tid & 15;   // 0..15

    const float* qb = qkv + (size_t)b * SS * 3 * DD + (size_t)h * HD;
    const float* kb = qb + DD;
    const float* vb = qb + 2 * DD;

    // load Q tile, transposed + pre-scaled
    for (int idx = tid; idx < 64 * HD; idx += 256) {
        int qq = idx / HD;
        int d = idx - qq * HD;
        int s = q0 + qq;
        sQ[d * 64 + qq] = (s < SS) ? qb[(size_t)s * 3 * DD + d] * SCALE_F : 0.f;
    }

    float acc[4][6];
#pragma unroll
    for (int i = 0; i < 4; i++)
#pragma unroll
        for (int j = 0; j < 6; j++) acc[i][j] = 0.f;
    float m_i[4], l_i[4];
#pragma unroll
    for (int i = 0; i < 4; i++) { m_i[i] = -1e30f; l_i[i] = 0.f; }

    __syncthreads();

    for (int kt0 = 0; kt0 < SS; kt0 += 64) {
        // load K (transposed) + V tiles
        for (int idx = tid; idx < 64 * HD; idx += 256) {
            int kk = idx / HD;
            int d = idx - kk * HD;
            int s = kt0 + kk;
            float kval = 0.f, vval = 0.f;
            if (s < SS) {
                kval = kb[(size_t)s * 3 * DD + d];
                vval = vb[(size_t)s * 3 * DD + d];
            }
            sK[d * 64 + kk] = kval;
            sV[kk * 96 + d] = vval;
        }
        __syncthreads();

        // scores: 4 queries x 4 keys per thread
        float sc[4][4];
#pragma unroll
        for (int i = 0; i < 4; i++)
#pragma unroll
            for (int j = 0; j < 4; j++) sc[i][j] = 0.f;

#pragma unroll 8
        for (int d = 0; d < HD; d++) {
            float4 qv = *(const float4*)&sQ[d * 64 + qg * 4];
            float4 kv = *(const float4*)&sK[d * 64 + kg * 4];
            float qa[4] = {qv.x, qv.y, qv.z, qv.w};
            float ka[4] = {kv.x, kv.y, kv.z, kv.w};
#pragma unroll
            for (int i = 0; i < 4; i++)
#pragma unroll
                for (int j = 0; j < 4; j++)
                    sc[i][j] = fmaf(qa[i], ka[j], sc[i][j]);
        }

        // mask out-of-range keys
#pragma unroll
        for (int j = 0; j < 4; j++) {
            if (kt0 + kg * 4 + j >= SS) {
#pragma unroll
                for (int i = 0; i < 4; i++) sc[i][j] = -1e30f;
            }
        }

        // online softmax update (row stats reduced across the 16 kg lanes,
        // which sit in one 16-lane half of a warp -> shfl_xor 8,4,2,1)
#pragma unroll
        for (int i = 0; i < 4; i++) {
            float mt = fmaxf(fmaxf(sc[i][0], sc[i][1]), fmaxf(sc[i][2], sc[i][3]));
#pragma unroll
            for (int off = 8; off > 0; off >>= 1)
                mt = fmaxf(mt, __shfl_xor_sync(0xffffffffu, mt, off));
            float mn = fmaxf(m_i[i], mt);
            float corr = __expf(m_i[i] - mn);
            float p[4];
            float ls = 0.f;
#pragma unroll
            for (int j = 0; j < 4; j++) {
                p[j] = __expf(sc[i][j] - mn);
                ls += p[j];
            }
#pragma unroll
            for (int off = 8; off > 0; off >>= 1)
                ls += __shfl_xor_sync(0xffffffffu, ls, off);
            l_i[i] = l_i[i] * corr + ls;
            m_i[i] = mn;
#pragma unroll
            for (int j = 0; j < 6; j++) acc[i][j] *= corr;
            // store P transposed: sP[key][query]
#pragma unroll
            for (int j = 0; j < 4; j++)
                sP[(kg * 4 + j) * 68 + qg * 4 + i] = p[j];
        }
        __syncthreads();

        // PV: thread (qg,kg) accumulates 4 queries x dims [kg*6, kg*6+6)
#pragma unroll 4
        for (int k = 0; k < 64; k++) {
            float4 p4 = *(const float4*)&sP[k * 68 + qg * 4];
            const float* vp = &sV[k * 96 + kg * 6];
            float pa[4] = {p4.x, p4.y, p4.z, p4.w};
#pragma unroll
            for (int j = 0; j < 6; j++) {
                float vv = vp[j];
#pragma unroll
                for (int i = 0; i < 4; i++)
                    acc[i][j] = fmaf(pa[i], vv, acc[i][j]);
            }
        }
        __syncthreads();
    }

    // epilogue
    float* ob = out + (size_t)b * SS * DD + (size_t)h * HD;
#pragma unroll
    for (int i = 0; i < 4; i++) {
        int s = q0 + qg * 4 + i;
        if (s >= SS) continue;
        float inv = 1.f / l_i[i];
#pragma unroll
        for (int j = 0; j < 6; j++) {
            int d = kg * 6 + j;
            if (d < HD) ob[(size_t)s * DD + d] = acc[i][j] * inv;
        }
    }
}

// ---------------------------------------------------------------------------
extern "C" void kernel_launch(void* const* d_in, const int* in_sizes, int n_in,
                              void* d_out, int out_size)
{
    const float* hs     = (const float*)d_in[0];
    const float* w_qkv  = (const float*)d_in[1];
    const float* b_qkv  = (const float*)d_in[2];
    const float* w_proj = (const float*)d_in[3];
    const float* b_proj = (const float*)d_in[4];
    float* out = (float*)d_out;

    float *qkv, *att;
    cudaGetSymbolAddress((void**)&qkv, g_qkv);
    cudaGetSymbolAddress((void**)&att, g_att);

    const int M = BB * SS;  // 9232

    // 1) QKV projection: [M, 1408] @ [1408, 4224] + bias
    dim3 g1((3 * DD) / 128, (M + 127) / 128);
    sgemm_bias_kernel<<<g1, 256>>>(hs, w_qkv, b_qkv, qkv, M, 3 * DD, DD);

    // 2) attention
    const size_t smem = (size_t)(2 * 88 * 64 + 64 * 96 + 64 * 68) * sizeof(float);  // 87,040 B
    cudaFuncSetAttribute(attn_kernel, cudaFuncAttributeMaxDynamicSharedMemorySize, (int)smem);
    dim3 g2((SS + 63) / 64, HH, BB);
    attn_kernel<<<g2, 256, smem>>>(qkv, att);

    // 3) output projection: [M, 1408] @ [1408, 1408] + bias
    dim3 g3(DD / 128, (M + 127) / 128);
    sgemm_bias_kernel<<<g3, 256>>>(att, w_proj, b_proj, out, M, DD, DD);
}

// round 3
// speedup vs baseline: 1.7105x; 1.7105x over previous
#include <cuda_runtime.h>
#include <cuda_bf16.h>
#include <cstdint>

// Problem constants
#define BB   16
#define SS   577
#define DD   1408
#define HH   16
#define HD   88
#define SCALE_F 0.10660035817780521f  // 1/sqrt(88)

#define MM   (BB * SS)      // 9232
#define N1   (3 * DD)       // 4224
#define KK   DD             // 1408

// ---------------------------------------------------------------------------
// Device-global scratch (allocation-free per harness rules)
// ---------------------------------------------------------------------------
__device__ float g_qkv[(size_t)MM * N1];
__device__ float g_att[(size_t)MM * DD];
__device__ __nv_bfloat16 g_hsH[(size_t)MM * KK];
__device__ __nv_bfloat16 g_hsL[(size_t)MM * KK];
__device__ __nv_bfloat16 g_attH[(size_t)MM * KK];
__device__ __nv_bfloat16 g_attL[(size_t)MM * KK];
__device__ __nv_bfloat16 g_wqkvH[(size_t)N1 * KK];   // transposed [N,K]
__device__ __nv_bfloat16 g_wqkvL[(size_t)N1 * KK];
__device__ __nv_bfloat16 g_wprojH[(size_t)DD * KK];  // transposed [N,K]
__device__ __nv_bfloat16 g_wprojL[(size_t)DD * KK];

// ---------------------------------------------------------------------------
// PTX helpers (standard sm_80+ instructions only — harness targets sm_103
// without the 'a' suffix, so tcgen05/TMEM are unavailable)
// ---------------------------------------------------------------------------
__device__ __forceinline__ uint32_t smem_to_u32(const void* p) {
    uint32_t a;
    asm("{ .reg .u64 t; cvta.to.shared.u64 t, %1; cvt.u32.u64 %0, t; }"
        : "=r"(a) : "l"(p));
    return a;
}
__device__ __forceinline__ void cp16(uint32_t dst, const void* src, uint32_t sz) {
    asm volatile("cp.async.ca.shared.global [%0], [%1], 16, %2;"
                 :: "r"(dst), "l"(src), "r"(sz) : "memory");
}
#define CP_COMMIT() asm volatile("cp.async.commit_group;" ::: "memory")
#define CP_WAIT(n)  asm volatile("cp.async.wait_group %0;" :: "n"(n) : "memory")

__device__ __forceinline__ void ldsm_x4(uint32_t* r, uint32_t addr) {
    asm volatile("ldmatrix.sync.aligned.m8n8.x4.shared.b16 {%0,%1,%2,%3}, [%4];"
                 : "=r"(r[0]), "=r"(r[1]), "=r"(r[2]), "=r"(r[3]) : "r"(addr));
}
__device__ __forceinline__ void ldsm_x2(uint32_t* r, uint32_t addr) {
    asm volatile("ldmatrix.sync.aligned.m8n8.x2.shared.b16 {%0,%1}, [%2];"
                 : "=r"(r[0]), "=r"(r[1]) : "r"(addr));
}
__device__ __forceinline__ void mma16816(float* d, const uint32_t* a, const uint32_t* b) {
    asm volatile("mma.sync.aligned.m16n8k16.row.col.f32.bf16.bf16.f32 "
                 "{%0,%1,%2,%3}, {%4,%5,%6,%7}, {%8,%9}, {%0,%1,%2,%3};"
                 : "+f"(d[0]), "+f"(d[1]), "+f"(d[2]), "+f"(d[3])
                 : "r"(a[0]), "r"(a[1]), "r"(a[2]), "r"(a[3]), "r"(b[0]), "r"(b[1]));
}

// ---------------------------------------------------------------------------
// Split fp32 -> (hi, lo) bf16, same layout.
// ---------------------------------------------------------------------------
__global__ void split_kernel(const float4* __restrict__ in,
                             uint2* __restrict__ hi, uint2* __restrict__ lo, int n4)
{
    int i = blockIdx.x * blockDim.x + threadIdx.x;
    if (i >= n4) return;
    float4 v = in[i];
    float x[4] = {v.x, v.y, v.z, v.w};
    __nv_bfloat16 h[4], l[4];
#pragma unroll
    for (int j = 0; j < 4; j++) {
        h[j] = __float2bfloat16(x[j]);
        l[j] = __float2bfloat16(x[j] - __bfloat162float(h[j]));
    }
    uint2 ho, loo;
    ho.x  = ((uint32_t)*(uint16_t*)&h[1] << 16) | *(uint16_t*)&h[0];
    ho.y  = ((uint32_t)*(uint16_t*)&h[3] << 16) | *(uint16_t*)&h[2];
    loo.x = ((uint32_t)*(uint16_t*)&l[1] << 16) | *(uint16_t*)&l[0];
    loo.y = ((uint32_t)*(uint16_t*)&l[3] << 16) | *(uint16_t*)&l[2];
    hi[i] = ho;
    lo[i] = loo;
}

// ---------------------------------------------------------------------------
// Transpose + split: in fp32 [R, C] -> hi/lo bf16 [C, R]
// ---------------------------------------------------------------------------
__global__ void tsplit_kernel(const float* __restrict__ in,
                              __nv_bfloat16* __restrict__ hi,
                              __nv_bfloat16* __restrict__ lo, int R, int C)
{
    __shared__ float t[32][33];
    int c0 = blockIdx.x * 32, r0 = blockIdx.y * 32;
    int tx = threadIdx.x, ty = threadIdx.y;
#pragma unroll
    for (int i = ty; i < 32; i += 8)
        t[i][tx] = in[(size_t)(r0 + i) * C + c0 + tx];
    __syncthreads();
#pragma unroll
    for (int i = ty; i < 32; i += 8) {
        float x = t[tx][i];
        __nv_bfloat16 h = __float2bfloat16(x);
        __nv_bfloat16 l = __float2bfloat16(x - __bfloat162float(h));
        size_t off = (size_t)(c0 + i) * R + r0 + tx;
        hi[off] = h;
        lo[off] = l;
    }
}

// ---------------------------------------------------------------------------
// bf16x3-split MMA GEMM + bias: C[M,N] = A[M,K] @ B[N,K]^T + bias[N]
// 128x128 CTA tile, BK=32, 3-stage cp.async pipeline, 8 warps (warp = 32x64),
// mma.sync.m16n8k16 with XOR-swizzled conflict-free ldmatrix.
// ---------------------------------------------------------------------------
#define BK      32
#define STAGES  3
#define TBYTES  8192                 // 128 rows * 64 bytes
#define STAGE_BYTES (4 * TBYTES)     // Ah | Al | Bh | Bl
#define NCH     (KK / BK)            // 44

// swizzled byte offset inside one tile: row r (0..127), 16B-chunk c (0..3)
__device__ __forceinline__ uint32_t swz(int r, int c) {
    return (uint32_t)(r * 64 + ((c ^ ((r >> 1) & 3)) << 4));
}

__global__ __launch_bounds__(256, 1) void gemm_mma_kernel(
    const __nv_bfloat16* __restrict__ Ahi, const __nv_bfloat16* __restrict__ Alo,
    const __nv_bfloat16* __restrict__ Bhi, const __nv_bfloat16* __restrict__ Blo,
    const float* __restrict__ bias, float* __restrict__ C, int M, int N)
{
    extern __shared__ char smem[];
    const uint32_t sbase = smem_to_u32(smem);

    const int tid = threadIdx.x;
    const int lane = tid & 31;
    const int wid = tid >> 5;
    const int wm = wid & 3;          // 4 warps along M
    const int wn = wid >> 2;         // 2 warps along N
    const int m0 = blockIdx.y * 128;
    const int n0 = blockIdx.x * 128;

    // ---- stage loader: 2048 16B-chunks per stage, 8 per thread ----
    auto load_stage = [&](int kt, int slot) {
        const int k0 = kt * BK;
        const uint32_t st = sbase + slot * STAGE_BYTES;
#pragma unroll
        for (int i = 0; i < 8; ++i) {
            int idx = tid + i * 256;
            int tile = idx >> 9;       // 0:Ah 1:Al 2:Bh 3:Bl
            int rem = idx & 511;
            int r = rem >> 2;
            int c = rem & 3;
            uint32_t dst = st + tile * TBYTES + swz(r, c);
            const __nv_bfloat16* gp;
            uint32_t sz = 16;
            if (tile < 2) {
                int m = m0 + r;
                int mc = m < M ? m : 0;
                if (m >= M) sz = 0;
                gp = (tile == 0 ? Ahi : Alo) + (size_t)mc * KK + k0 + c * 8;
            } else {
                int n = n0 + r;        // N is a multiple of 128
                gp = (tile == 2 ? Bhi : Blo) + (size_t)n * KK + k0 + c * 8;
            }
            cp16(dst, gp, sz);
        }
        CP_COMMIT();
    };

    float acc[2][8][4];
#pragma unroll
    for (int t = 0; t < 2; ++t)
#pragma unroll
        for (int j = 0; j < 8; ++j)
#pragma unroll
            for (int v = 0; v < 4; ++v) acc[t][j][v] = 0.f;

    // prologue: fill first STAGES-1 stages
    load_stage(0, 0);
    load_stage(1, 1);

    for (int kt = 0; kt < NCH; ++kt) {
        CP_WAIT(1);
        __syncthreads();
        if (kt + 2 < NCH) load_stage(kt + 2, (kt + 2) % STAGES);

        const uint32_t st = sbase + (kt % STAGES) * STAGE_BYTES;
#pragma unroll
        for (int ks = 0; ks < 2; ++ks) {
            uint32_t ah[2][4], al[2][4], bh[8][2], bl[8][2];
#pragma unroll
            for (int t = 0; t < 2; ++t) {
                int r = wm * 32 + t * 16 + (lane & 15);
                int c = ks * 2 + (lane >> 4);
                uint32_t off = swz(r, c);
                ldsm_x4(ah[t], st + 0 * TBYTES + off);
                ldsm_x4(al[t], st + 1 * TBYTES + off);
            }
#pragma unroll
            for (int j = 0; j < 8; ++j) {
                int r = wn * 64 + j * 8 + (lane & 7);
                int c = ks * 2 + ((lane >> 3) & 1);
                uint32_t off = swz(r, c);
                ldsm_x2(bh[j], st + 2 * TBYTES + off);
                ldsm_x2(bl[j], st + 3 * TBYTES + off);
            }
#pragma unroll
            for (int t = 0; t < 2; ++t)
#pragma unroll
                for (int j = 0; j < 8; ++j) {
                    mma16816(acc[t][j], ah[t], bh[j]);
                    mma16816(acc[t][j], ah[t], bl[j]);
                    mma16816(acc[t][j], al[t], bh[j]);
                }
        }
    }

    // epilogue: fused bias, direct fp32 stores
    const int rb = m0 + wm * 32 + (lane >> 2);
    const int cb = n0 + wn * 64 + (lane & 3) * 2;
#pragma unroll
    for (int t = 0; t < 2; ++t) {
        int r0 = rb + t * 16;
#pragma unroll
        for (int j = 0; j < 8; ++j) {
            int col = cb + j * 8;
            float2 b2 = *(const float2*)&bias[col];
            if (r0 < M) {
                float2 o = {acc[t][j][0] + b2.x, acc[t][j][1] + b2.y};
                *(float2*)&C[(size_t)r0 * N + col] = o;
            }
            if (r0 + 8 < M) {
                float2 o = {acc[t][j][2] + b2.x, acc[t][j][3] + b2.y};
                *(float2*)&C[(size_t)(r0 + 8) * N + col] = o;
            }
        }
    }
}

// ---------------------------------------------------------------------------
// Flash-style attention (fp32, unchanged from R1)
// ---------------------------------------------------------------------------
__global__ __launch_bounds__(256) void attn_kernel(
    const float* __restrict__ qkv, float* __restrict__ out)
{
    extern __shared__ float sm[];
    float* sQ = sm;
    float* sK = sm + 88 * 64;
    float* sV = sm + 2 * 88 * 64;
    float* sP = sm + 2 * 88 * 64 + 64 * 96;

    const int b = blockIdx.z;
    const int h = blockIdx.y;
    const int q0 = blockIdx.x * 64;
    const int tid = threadIdx.x;
    const int qg = tid >> 4;
    const int kg = tid & 15;

    const float* qb = qkv + (size_t)b * SS * 3 * DD + (size_t)h * HD;
    const float* kb = qb + DD;
    const float* vb = qb + 2 * DD;

    for (int idx = tid; idx < 64 * HD; idx += 256) {
        int qq = idx / HD;
        int d = idx - qq * HD;
        int s = q0 + qq;
        sQ[d * 64 + qq] = (s < SS) ? qb[(size_t)s * 3 * DD + d] * SCALE_F : 0.f;
    }

    float acc[4][6];
#pragma unroll
    for (int i = 0; i < 4; i++)
#pragma unroll
        for (int j = 0; j < 6; j++) acc[i][j] = 0.f;
    float m_i[4], l_i[4];
#pragma unroll
    for (int i = 0; i < 4; i++) { m_i[i] = -1e30f; l_i[i] = 0.f; }

    __syncthreads();

    for (int kt0 = 0; kt0 < SS; kt0 += 64) {
        for (int idx = tid; idx < 64 * HD; idx += 256) {
            int kk = idx / HD;
            int d = idx - kk * HD;
            int s = kt0 + kk;
            float kval = 0.f, vval = 0.f;
            if (s < SS) {
                kval = kb[(size_t)s * 3 * DD + d];
                vval = vb[(size_t)s * 3 * DD + d];
            }
            sK[d * 64 + kk] = kval;
            sV[kk * 96 + d] = vval;
        }
        __syncthreads();

        float sc[4][4];
#pragma unroll
        for (int i = 0; i < 4; i++)
#pragma unroll
            for (int j = 0; j < 4; j++) sc[i][j] = 0.f;

#pragma unroll 8
        for (int d = 0; d < HD; d++) {
            float4 qv = *(const float4*)&sQ[d * 64 + qg * 4];
            float4 kv = *(const float4*)&sK[d * 64 + kg * 4];
            float qa[4] = {qv.x, qv.y, qv.z, qv.w};
            float ka[4] = {kv.x, kv.y, kv.z, kv.w};
#pragma unroll
            for (int i = 0; i < 4; i++)
#pragma unroll
                for (int j = 0; j < 4; j++)
                    sc[i][j] = fmaf(qa[i], ka[j], sc[i][j]);
        }

#pragma unroll
        for (int j = 0; j < 4; j++) {
            if (kt0 + kg * 4 + j >= SS) {
#pragma unroll
                for (int i = 0; i < 4; i++) sc[i][j] = -1e30f;
            }
        }

#pragma unroll
        for (int i = 0; i < 4; i++) {
            float mt = fmaxf(fmaxf(sc[i][0], sc[i][1]), fmaxf(sc[i][2], sc[i][3]));
#pragma unroll
            for (int off = 8; off > 0; off >>= 1)
                mt = fmaxf(mt, __shfl_xor_sync(0xffffffffu, mt, off));
            float mn = fmaxf(m_i[i], mt);
            float corr = __expf(m_i[i] - mn);
            float p[4];
            float ls = 0.f;
#pragma unroll
            for (int j = 0; j < 4; j++) {
                p[j] = __expf(sc[i][j] - mn);
                ls += p[j];
            }
#pragma unroll
            for (int off = 8; off > 0; off >>= 1)
                ls += __shfl_xor_sync(0xffffffffu, ls, off);
            l_i[i] = l_i[i] * corr + ls;
            m_i[i] = mn;
#pragma unroll
            for (int j = 0; j < 6; j++) acc[i][j] *= corr;
#pragma unroll
            for (int j = 0; j < 4; j++)
                sP[(kg * 4 + j) * 68 + qg * 4 + i] = p[j];
        }
        __syncthreads();

#pragma unroll 4
        for (int k = 0; k < 64; k++) {
            float4 p4 = *(const float4*)&sP[k * 68 + qg * 4];
            const float* vp = &sV[k * 96 + kg * 6];
            float pa[4] = {p4.x, p4.y, p4.z, p4.w};
#pragma unroll
            for (int j = 0; j < 6; j++) {
                float vv = vp[j];
#pragma unroll
                for (int i = 0; i < 4; i++)
                    acc[i][j] = fmaf(pa[i], vv, acc[i][j]);
            }
        }
        __syncthreads();
    }

    float* ob = out + (size_t)b * SS * DD + (size_t)h * HD;
#pragma unroll
    for (int i = 0; i < 4; i++) {
        int s = q0 + qg * 4 + i;
        if (s >= SS) continue;
        float inv = 1.f / l_i[i];
#pragma unroll
        for (int j = 0; j < 6; j++) {
            int d = kg * 6 + j;
            if (d < HD) ob[(size_t)s * DD + d] = acc[i][j] * inv;
        }
    }
}

// ---------------------------------------------------------------------------
extern "C" void kernel_launch(void* const* d_in, const int* in_sizes, int n_in,
                              void* d_out, int out_size)
{
    const float* hs     = (const float*)d_in[0];
    const float* w_qkv  = (const float*)d_in[1];
    const float* b_qkv  = (const float*)d_in[2];
    const float* w_proj = (const float*)d_in[3];
    const float* b_proj = (const float*)d_in[4];
    float* out = (float*)d_out;

    float *qkv, *att;
    __nv_bfloat16 *hsH, *hsL, *attH, *attL, *wqH, *wqL, *wpH, *wpL;
    cudaGetSymbolAddress((void**)&qkv, g_qkv);
    cudaGetSymbolAddress((void**)&att, g_att);
    cudaGetSymbolAddress((void**)&hsH, g_hsH);
    cudaGetSymbolAddress((void**)&hsL, g_hsL);
    cudaGetSymbolAddress((void**)&attH, g_attH);
    cudaGetSymbolAddress((void**)&attL, g_attL);
    cudaGetSymbolAddress((void**)&wqH, g_wqkvH);
    cudaGetSymbolAddress((void**)&wqL, g_wqkvL);
    cudaGetSymbolAddress((void**)&wpH, g_wprojH);
    cudaGetSymbolAddress((void**)&wpL, g_wprojL);

    const int gemm_smem = STAGES * STAGE_BYTES;   // 96 KB
    cudaFuncSetAttribute(gemm_mma_kernel, cudaFuncAttributeMaxDynamicSharedMemorySize, gemm_smem);

    // 0a) split hidden_states
    {
        int n4 = MM * KK / 4;
        split_kernel<<<(n4 + 255) / 256, 256>>>((const float4*)hs, (uint2*)hsH, (uint2*)hsL, n4);
    }
    // 0b) transpose+split w_qkv [K,N1] -> [N1,K]
    {
        dim3 g(N1 / 32, KK / 32);
        tsplit_kernel<<<g, dim3(32, 8)>>>(w_qkv, wqH, wqL, KK, N1);
    }
    // 1) QKV projection (tensor cores via mma.sync)
    {
        dim3 g(N1 / 128, (MM + 127) / 128);
        gemm_mma_kernel<<<g, 256, gemm_smem>>>(hsH, hsL, wqH, wqL, b_qkv, qkv, MM, N1);
    }
    // 2) attention
    {
        const size_t smem = (size_t)(2 * 88 * 64 + 64 * 96 + 64 * 68) * sizeof(float);
        cudaFuncSetAttribute(attn_kernel, cudaFuncAttributeMaxDynamicSharedMemorySize, (int)smem);
        dim3 g((SS + 63) / 64, HH, BB);
        attn_kernel<<<g, 256, smem>>>(qkv, att);
    }
    // 3a) split attention output
    {
        int n4 = MM * KK / 4;
        split_kernel<<<(n4 + 255) / 256, 256>>>((const float4*)att, (uint2*)attH, (uint2*)attL, n4);
    }
    // 3b) transpose+split w_proj [K,D] -> [D,K]
    {
        dim3 g(DD / 32, KK / 32);
        tsplit_kernel<<<g, dim3(32, 8)>>>(w_proj, wpH, wpL, KK, DD);
    }
    // 4) output projection
    {
        dim3 g(DD / 128, (MM + 127) / 128);
        gemm_mma_kernel<<<g, 256, gemm_smem>>>(attH, attL, wpH, wpL, b_proj, out, MM, DD);
    }
}

// round 4
// speedup vs baseline: 2.6802x; 1.5669x over previous
#include <cuda_runtime.h>
#include <cuda_bf16.h>
#include <cstdint>

// Problem constants
#define BB   16
#define SS   577
#define DD   1408
#define HH   16
#define HD   88
#define SCALE_F 0.10660035817780521f  // 1/sqrt(88)

#define MM   (BB * SS)      // 9232
#define N1   (3 * DD)       // 4224
#define KK   DD             // 1408

// ---------------------------------------------------------------------------
// Device-global scratch
// ---------------------------------------------------------------------------
__device__ __nv_bfloat16 g_hsH[(size_t)MM * KK];
__device__ __nv_bfloat16 g_hsL[(size_t)MM * KK];
__device__ __nv_bfloat16 g_qkvH[(size_t)MM * N1];
__device__ __nv_bfloat16 g_qkvL[(size_t)MM * N1];
__device__ __nv_bfloat16 g_attH[(size_t)MM * KK];
__device__ __nv_bfloat16 g_attL[(size_t)MM * KK];
__device__ __nv_bfloat16 g_wqkvH[(size_t)N1 * KK];   // transposed [N,K]
__device__ __nv_bfloat16 g_wqkvL[(size_t)N1 * KK];
__device__ __nv_bfloat16 g_wprojH[(size_t)DD * KK];  // transposed [N,K]
__device__ __nv_bfloat16 g_wprojL[(size_t)DD * KK];

// ---------------------------------------------------------------------------
// PTX helpers (sm_80+ only; harness targets sm_103 w/o 'a' — no tcgen05)
// ---------------------------------------------------------------------------
__device__ __forceinline__ uint32_t smem_to_u32(const void* p) {
    uint32_t a;
    asm("{ .reg .u64 t; cvta.to.shared.u64 t, %1; cvt.u32.u64 %0, t; }"
        : "=r"(a) : "l"(p));
    return a;
}
__device__ __forceinline__ void cp16(uint32_t dst, const void* src, uint32_t sz) {
    asm volatile("cp.async.ca.shared.global [%0], [%1], 16, %2;"
                 :: "r"(dst), "l"(src), "r"(sz) : "memory");
}
#define CP_COMMIT() asm volatile("cp.async.commit_group;" ::: "memory")
#define CP_WAIT(n)  asm volatile("cp.async.wait_group %0;" :: "n"(n) : "memory")

__device__ __forceinline__ void ldsm_x4(uint32_t* r, uint32_t addr) {
    asm volatile("ldmatrix.sync.aligned.m8n8.x4.shared.b16 {%0,%1,%2,%3}, [%4];"
                 : "=r"(r[0]), "=r"(r[1]), "=r"(r[2]), "=r"(r[3]) : "r"(addr));
}
__device__ __forceinline__ void ldsm_x2(uint32_t* r, uint32_t addr) {
    asm volatile("ldmatrix.sync.aligned.m8n8.x2.shared.b16 {%0,%1}, [%2];"
                 : "=r"(r[0]), "=r"(r[1]) : "r"(addr));
}
__device__ __forceinline__ void ldsm_x2t(uint32_t* r, uint32_t addr) {
    asm volatile("ldmatrix.sync.aligned.m8n8.x2.trans.shared.b16 {%0,%1}, [%2];"
                 : "=r"(r[0]), "=r"(r[1]) : "r"(addr));
}
__device__ __forceinline__ void mma16816(float* d, const uint32_t* a, const uint32_t* b) {
    asm volatile("mma.sync.aligned.m16n8k16.row.col.f32.bf16.bf16.f32 "
                 "{%0,%1,%2,%3}, {%4,%5,%6,%7}, {%8,%9}, {%0,%1,%2,%3};"
                 : "+f"(d[0]), "+f"(d[1]), "+f"(d[2]), "+f"(d[3])
                 : "r"(a[0]), "r"(a[1]), "r"(a[2]), "r"(a[3]), "r"(b[0]), "r"(b[1]));
}
__device__ __forceinline__ uint32_t pack_bf16x2(float a, float b) {
    __nv_bfloat16 ha = __float2bfloat16(a), hb = __float2bfloat16(b);
    return ((uint32_t)*(uint16_t*)&hb << 16) | *(uint16_t*)&ha;
}
__device__ __forceinline__ void split_pair(float a, float b, uint32_t& hi, uint32_t& lo) {
    __nv_bfloat16 ha = __float2bfloat16(a), hb = __float2bfloat16(b);
    float la = a - __bfloat162float(ha), lb = b - __bfloat162float(hb);
    __nv_bfloat16 hla = __float2bfloat16(la), hlb = __float2bfloat16(lb);
    hi = ((uint32_t)*(uint16_t*)&hb << 16) | *(uint16_t*)&ha;
    lo = ((uint32_t)*(uint16_t*)&hlb << 16) | *(uint16_t*)&hla;
}

// ---------------------------------------------------------------------------
// Split fp32 -> (hi, lo) bf16, same layout.
// ---------------------------------------------------------------------------
__global__ void split_kernel(const float4* __restrict__ in,
                             uint2* __restrict__ hi, uint2* __restrict__ lo, int n4)
{
    int i = blockIdx.x * blockDim.x + threadIdx.x;
    if (i >= n4) return;
    float4 v = in[i];
    uint2 ho, loo;
    split_pair(v.x, v.y, ho.x, loo.x);
    split_pair(v.z, v.w, ho.y, loo.y);
    hi[i] = ho;
    lo[i] = loo;
}

// ---------------------------------------------------------------------------
// Transpose + split: in fp32 [R, C] -> hi/lo bf16 [C, R]
// ---------------------------------------------------------------------------
__global__ void tsplit_kernel(const float* __restrict__ in,
                              __nv_bfloat16* __restrict__ hi,
                              __nv_bfloat16* __restrict__ lo, int R, int C)
{
    __shared__ float t[32][33];
    int c0 = blockIdx.x * 32, r0 = blockIdx.y * 32;
    int tx = threadIdx.x, ty = threadIdx.y;
#pragma unroll
    for (int i = ty; i < 32; i += 8)
        t[i][tx] = in[(size_t)(r0 + i) * C + c0 + tx];
    __syncthreads();
#pragma unroll
    for (int i = ty; i < 32; i += 8) {
        float x = t[tx][i];
        __nv_bfloat16 h = __float2bfloat16(x);
        __nv_bfloat16 l = __float2bfloat16(x - __bfloat162float(h));
        size_t off = (size_t)(c0 + i) * R + r0 + tx;
        hi[off] = h;
        lo[off] = l;
    }
}

// ---------------------------------------------------------------------------
// bf16x3-split MMA GEMM: C[M,N] = A[M,K] @ B[N,K]^T + bias[N]
// MODE 0: fp32 C out.  MODE 1: bf16 hi/lo out, cols<DD scaled by SCALE_F.
// ---------------------------------------------------------------------------
#define BK      32
#define STAGES  3
#define TBYTES  8192
#define STAGE_BYTES (4 * TBYTES)
#define NCH     (KK / BK)

__device__ __forceinline__ uint32_t swz(int r, int c) {
    return (uint32_t)(r * 64 + ((c ^ ((r >> 1) & 3)) << 4));
}

template<int MODE>
__global__ __launch_bounds__(256, 1) void gemm_mma_kernel(
    const __nv_bfloat16* __restrict__ Ahi, const __nv_bfloat16* __restrict__ Alo,
    const __nv_bfloat16* __restrict__ Bhi, const __nv_bfloat16* __restrict__ Blo,
    const float* __restrict__ bias, float* __restrict__ C,
    __nv_bfloat16* __restrict__ CH, __nv_bfloat16* __restrict__ CL,
    int M, int N)
{
    extern __shared__ char smem[];
    const uint32_t sbase = smem_to_u32(smem);

    const int tid = threadIdx.x;
    const int lane = tid & 31;
    const int wid = tid >> 5;
    const int wm = wid & 3;
    const int wn = wid >> 2;
    const int m0 = blockIdx.y * 128;
    const int n0 = blockIdx.x * 128;

    auto load_stage = [&](int kt, int slot) {
        const int k0 = kt * BK;
        const uint32_t st = sbase + slot * STAGE_BYTES;
#pragma unroll
        for (int i = 0; i < 8; ++i) {
            int idx = tid + i * 256;
            int tile = idx >> 9;
            int rem = idx & 511;
            int r = rem >> 2;
            int c = rem & 3;
            uint32_t dst = st + tile * TBYTES + swz(r, c);
            const __nv_bfloat16* gp;
            uint32_t sz = 16;
            if (tile < 2) {
                int m = m0 + r;
                int mc = m < M ? m : 0;
                if (m >= M) sz = 0;
                gp = (tile == 0 ? Ahi : Alo) + (size_t)mc * KK + k0 + c * 8;
            } else {
                int n = n0 + r;
                gp = (tile == 2 ? Bhi : Blo) + (size_t)n * KK + k0 + c * 8;
            }
            cp16(dst, gp, sz);
        }
        CP_COMMIT();
    };

    float acc[2][8][4];
#pragma unroll
    for (int t = 0; t < 2; ++t)
#pragma unroll
        for (int j = 0; j < 8; ++j)
#pragma unroll
            for (int v = 0; v < 4; ++v) acc[t][j][v] = 0.f;

    load_stage(0, 0);
    load_stage(1, 1);

    for (int kt = 0; kt < NCH; ++kt) {
        CP_WAIT(1);
        __syncthreads();
        if (kt + 2 < NCH) load_stage(kt + 2, (kt + 2) % STAGES);

        const uint32_t st = sbase + (kt % STAGES) * STAGE_BYTES;
#pragma unroll
        for (int ks = 0; ks < 2; ++ks) {
            uint32_t ah[2][4], al[2][4], bh[8][2], bl[8][2];
#pragma unroll
            for (int t = 0; t < 2; ++t) {
                int r = wm * 32 + t * 16 + (lane & 15);
                int c = ks * 2 + (lane >> 4);
                uint32_t off = swz(r, c);
                ldsm_x4(ah[t], st + 0 * TBYTES + off);
                ldsm_x4(al[t], st + 1 * TBYTES + off);
            }
#pragma unroll
            for (int j = 0; j < 8; ++j) {
                int r = wn * 64 + j * 8 + (lane & 7);
                int c = ks * 2 + ((lane >> 3) & 1);
                uint32_t off = swz(r, c);
                ldsm_x2(bh[j], st + 2 * TBYTES + off);
                ldsm_x2(bl[j], st + 3 * TBYTES + off);
            }
#pragma unroll
            for (int t = 0; t < 2; ++t)
#pragma unroll
                for (int j = 0; j < 8; ++j) {
                    mma16816(acc[t][j], ah[t], bh[j]);
                    mma16816(acc[t][j], ah[t], bl[j]);
                    mma16816(acc[t][j], al[t], bh[j]);
                }
        }
    }

    const int rb = m0 + wm * 32 + (lane >> 2);
    const int cb = n0 + wn * 64 + (lane & 3) * 2;
#pragma unroll
    for (int t = 0; t < 2; ++t) {
        int r0 = rb + t * 16;
#pragma unroll
        for (int j = 0; j < 8; ++j) {
            int col = cb + j * 8;
            float2 b2 = *(const float2*)&bias[col];
            if constexpr (MODE == 0) {
                if (r0 < M) {
                    float2 o = {acc[t][j][0] + b2.x, acc[t][j][1] + b2.y};
                    *(float2*)&C[(size_t)r0 * N + col] = o;
                }
                if (r0 + 8 < M) {
                    float2 o = {acc[t][j][2] + b2.x, acc[t][j][3] + b2.y};
                    *(float2*)&C[(size_t)(r0 + 8) * N + col] = o;
                }
            } else {
                float s = (col < DD) ? SCALE_F : 1.0f;
                if (r0 < M) {
                    uint32_t hi, lo;
                    split_pair((acc[t][j][0] + b2.x) * s, (acc[t][j][1] + b2.y) * s, hi, lo);
                    *(uint32_t*)&CH[(size_t)r0 * N + col] = hi;
                    *(uint32_t*)&CL[(size_t)r0 * N + col] = lo;
                }
                if (r0 + 8 < M) {
                    uint32_t hi, lo;
                    split_pair((acc[t][j][2] + b2.x) * s, (acc[t][j][3] + b2.y) * s, hi, lo);
                    *(uint32_t*)&CH[(size_t)(r0 + 8) * N + col] = hi;
                    *(uint32_t*)&CL[(size_t)(r0 + 8) * N + col] = lo;
                }
            }
        }
    }
}

// ---------------------------------------------------------------------------
// Tensor-core flash attention.
// CTA = (b, h, 128-query tile). 8 warps = 4(M) x 2(N).
// QK^T and P.V via mma.sync bf16 with 2-term hi/lo split (3 MMAs each).
// smem rows: Q/K/V 192B (96 cols, cols 88-95 zero), P 128B (64 keys).
// ---------------------------------------------------------------------------
#define SM_QH   0
#define SM_QL   24576
#define SM_KV   49152           // 2 bufs x (Kh|Kl|Vh|Vl) 12288 each = 49152/buf
#define SM_PH   147456
#define SM_PL   163840
#define SM_STAT 180224          // sMax[2][128] f32, sSum[2][128] f32
#define SM_ATT_TOTAL 182272

__device__ __forceinline__ uint32_t swzQ(int r, int c) {   // 192B rows, c 0..11
    return (uint32_t)(r * 192 + ((c ^ ((r >> 1) & 3)) << 4));
}
__device__ __forceinline__ uint32_t swzP(int r, int c) {   // 128B rows, c 0..7
    return (uint32_t)(r * 128 + ((c ^ (r & 7)) << 4));
}

__global__ __launch_bounds__(256, 1) void attn_tc_kernel(
    const __nv_bfloat16* __restrict__ qkvH, const __nv_bfloat16* __restrict__ qkvL,
    __nv_bfloat16* __restrict__ attH, __nv_bfloat16* __restrict__ attL)
{
    extern __shared__ char smem[];
    const uint32_t sb = smem_to_u32(smem);
    const int tid = threadIdx.x;
    const int lane = tid & 31;
    const int wid = tid >> 5;
    const int wm = wid & 3;
    const int wn = wid >> 2;
    const int b = blockIdx.z;
    const int h = blockIdx.y;
    const int q0 = blockIdx.x * 128;

    float* sMax = (float*)(smem + SM_STAT);          // [2][128]
    float* sSum = (float*)(smem + SM_STAT + 1024);   // [2][128]

    const size_t rowbase = (size_t)b * SS * N1 + (size_t)h * HD;

    // Q: 128 rows x 12 chunks x {hi,lo}. 2 threads/row, 6 chunks each.
    {
        int r = tid >> 1;
        int cbase = (tid & 1) * 6;
        int s = q0 + r;
        int sc_ = s < SS ? s : SS - 1;
        const __nv_bfloat16* srcH = qkvH + rowbase + (size_t)sc_ * N1;
        const __nv_bfloat16* srcL = qkvL + rowbase + (size_t)sc_ * N1;
#pragma unroll
        for (int cc = 0; cc < 6; ++cc) {
            int c = cbase + cc;
            int ca = c < 11 ? c : 10;
            uint32_t sz = (c < 11 && s < SS) ? 16 : 0;
            cp16(sb + SM_QH + swzQ(r, c), srcH + ca * 8, sz);
            cp16(sb + SM_QL + swzQ(r, c), srcL + ca * 8, sz);
        }
    }

    // KV loader: 64 rows x 12 chunks x 4 arrays. 4 threads/row, 3 chunks x 4 arrays.
    auto load_kv = [&](int kt, int buf) {
        int r = tid >> 2;
        int cbase = (tid & 3) * 3;
        int s = kt * 64 + r;
        int sc_ = s < SS ? s : SS - 1;
        const uint32_t kb = sb + SM_KV + buf * 49152;
        const __nv_bfloat16* base[4] = {
            qkvH + rowbase + (size_t)sc_ * N1 + DD,
            qkvL + rowbase + (size_t)sc_ * N1 + DD,
            qkvH + rowbase + (size_t)sc_ * N1 + 2 * DD,
            qkvL + rowbase + (size_t)sc_ * N1 + 2 * DD
        };
#pragma unroll
        for (int arr = 0; arr < 4; ++arr) {
#pragma unroll
            for (int cc = 0; cc < 3; ++cc) {
                int c = cbase + cc;
                int ca = c < 11 ? c : 10;
                uint32_t sz = (c < 11 && s < SS) ? 16 : 0;
                cp16(kb + arr * 12288 + swzQ(r, c), base[arr] + ca * 8, sz);
            }
        }
    };

    load_kv(0, 0);
    CP_COMMIT();

    float acc[2][6][4];
#pragma unroll
    for (int ti = 0; ti < 2; ++ti)
#pragma unroll
        for (int j = 0; j < 6; ++j)
#pragma unroll
            for (int v = 0; v < 4; ++v) acc[ti][j][v] = 0.f;
    float m_old[2][2] = {{-1e30f, -1e30f}, {-1e30f, -1e30f}};
    float l_run[2][2] = {{0.f, 0.f}, {0.f, 0.f}};

    const int NKT = (SS + 63) / 64;   // 10

    for (int kt = 0; kt < NKT; ++kt) {
        CP_WAIT(0);
        __syncthreads();
        if (kt + 1 < NKT) load_kv(kt + 1, (kt + 1) & 1);
        CP_COMMIT();

        const uint32_t kb = sb + SM_KV + (kt & 1) * 49152;

        // ---- QK^T ----
        float sc[2][4][4];
#pragma unroll
        for (int ti = 0; ti < 2; ++ti)
#pragma unroll
            for (int j = 0; j < 4; ++j)
#pragma unroll
                for (int v = 0; v < 4; ++v) sc[ti][j][v] = 0.f;

#pragma unroll
        for (int ks = 0; ks < 6; ++ks) {
            uint32_t ah[2][4], al[2][4], bh[4][2], bl[4][2];
#pragma unroll
            for (int ti = 0; ti < 2; ++ti) {
                int r = wm * 32 + ti * 16 + (lane & 15);
                int c = ks * 2 + (lane >> 4);
                uint32_t off = swzQ(r, c);
                ldsm_x4(ah[ti], sb + SM_QH + off);
                ldsm_x4(al[ti], sb + SM_QL + off);
            }
#pragma unroll
            for (int j = 0; j < 4; ++j) {
                int r = wn * 32 + j * 8 + (lane & 7);
                int c = ks * 2 + ((lane >> 3) & 1);
                uint32_t off = swzQ(r, c);
                ldsm_x2(bh[j], kb + 0 + off);
                ldsm_x2(bl[j], kb + 12288 + off);
            }
#pragma unroll
            for (int ti = 0; ti < 2; ++ti)
#pragma unroll
                for (int j = 0; j < 4; ++j) {
                    mma16816(sc[ti][j], ah[ti], bh[j]);
                    mma16816(sc[ti][j], ah[ti], bl[j]);
                    mma16816(sc[ti][j], al[ti], bh[j]);
                }
        }

        // ---- mask ----
#pragma unroll
        for (int j = 0; j < 4; ++j) {
            int c0 = kt * 64 + wn * 32 + j * 8 + (lane & 3) * 2;
            if (c0 >= SS) { sc[0][j][0] = sc[0][j][2] = sc[1][j][0] = sc[1][j][2] = -1e30f; }
            if (c0 + 1 >= SS) { sc[0][j][1] = sc[0][j][3] = sc[1][j][1] = sc[1][j][3] = -1e30f; }
        }

        // ---- row max (cross-warp via smem) ----
#pragma unroll
        for (int ti = 0; ti < 2; ++ti)
#pragma unroll
            for (int hh = 0; hh < 2; ++hh) {
                float mt = -1e30f;
#pragma unroll
                for (int j = 0; j < 4; ++j)
                    mt = fmaxf(mt, fmaxf(sc[ti][j][hh * 2], sc[ti][j][hh * 2 + 1]));
                mt = fmaxf(mt, __shfl_xor_sync(0xffffffffu, mt, 1));
                mt = fmaxf(mt, __shfl_xor_sync(0xffffffffu, mt, 2));
                if ((lane & 3) == 0) {
                    int rl = wm * 32 + ti * 16 + hh * 8 + (lane >> 2);
                    sMax[wn * 128 + rl] = mt;
                }
            }
        __syncthreads();

        float mnew[2][2], corr[2][2];
#pragma unroll
        for (int ti = 0; ti < 2; ++ti)
#pragma unroll
            for (int hh = 0; hh < 2; ++hh) {
                int rl = wm * 32 + ti * 16 + hh * 8 + (lane >> 2);
                float m2 = fmaxf(sMax[rl], sMax[128 + rl]);
                float mn = fmaxf(m_old[ti][hh], m2);
                corr[ti][hh] = __expf(m_old[ti][hh] - mn);
                mnew[ti][hh] = mn;
                m_old[ti][hh] = mn;
            }

        // ---- exp, P store (hi/lo), sums ----
        float sum_[2][2] = {{0.f, 0.f}, {0.f, 0.f}};
#pragma unroll
        for (int ti = 0; ti < 2; ++ti) {
            int r0 = wm * 32 + ti * 16 + (lane >> 2);
#pragma unroll
            for (int j = 0; j < 4; ++j) {
                float p0 = __expf(sc[ti][j][0] - mnew[ti][0]);
                float p1 = __expf(sc[ti][j][1] - mnew[ti][0]);
                float p2 = __expf(sc[ti][j][2] - mnew[ti][1]);
                float p3 = __expf(sc[ti][j][3] - mnew[ti][1]);
                sum_[ti][0] += p0 + p1;
                sum_[ti][1] += p2 + p3;
                int colc = wn * 32 + j * 8 + (lane & 3) * 2;
                uint32_t o0 = swzP(r0, colc >> 3) + (colc & 7) * 2;
                uint32_t o1 = swzP(r0 + 8, colc >> 3) + (colc & 7) * 2;
                uint32_t hi, lo;
                split_pair(p0, p1, hi, lo);
                *(uint32_t*)(smem + SM_PH + o0) = hi;
                *(uint32_t*)(smem + SM_PL + o0) = lo;
                split_pair(p2, p3, hi, lo);
                *(uint32_t*)(smem + SM_PH + o1) = hi;
                *(uint32_t*)(smem + SM_PL + o1) = lo;
            }
        }
#pragma unroll
        for (int ti = 0; ti < 2; ++ti)
#pragma unroll
            for (int hh = 0; hh < 2; ++hh) {
                float s = sum_[ti][hh];
                s += __shfl_xor_sync(0xffffffffu, s, 1);
                s += __shfl_xor_sync(0xffffffffu, s, 2);
                if ((lane & 3) == 0) {
                    int rl = wm * 32 + ti * 16 + hh * 8 + (lane >> 2);
                    sSum[wn * 128 + rl] = s;
                }
            }
        // rescale accumulator
#pragma unroll
        for (int ti = 0; ti < 2; ++ti)
#pragma unroll
            for (int j = 0; j < 6; ++j) {
                acc[ti][j][0] *= corr[ti][0];
                acc[ti][j][1] *= corr[ti][0];
                acc[ti][j][2] *= corr[ti][1];
                acc[ti][j][3] *= corr[ti][1];
            }
        __syncthreads();
#pragma unroll
        for (int ti = 0; ti < 2; ++ti)
#pragma unroll
            for (int hh = 0; hh < 2; ++hh) {
                int rl = wm * 32 + ti * 16 + hh * 8 + (lane >> 2);
                l_run[ti][hh] = l_run[ti][hh] * corr[ti][hh] + sSum[rl] + sSum[128 + rl];
            }

        // ---- P.V ----
#pragma unroll
        for (int ks = 0; ks < 4; ++ks) {
            uint32_t ph[2][4], pl[2][4], vh[6][2], vl[6][2];
#pragma unroll
            for (int ti = 0; ti < 2; ++ti) {
                int r = wm * 32 + ti * 16 + (lane & 15);
                int c = ks * 2 + (lane >> 4);
                uint32_t off = swzP(r, c);
                ldsm_x4(ph[ti], sb + SM_PH + off);
                ldsm_x4(pl[ti], sb + SM_PL + off);
            }
#pragma unroll
            for (int j = 0; j < 6; ++j) {
                int rk = ks * 16 + (lane & 15);
                int c = wn * 6 + j;
                uint32_t off = swzQ(rk, c);
                ldsm_x2t(vh[j], kb + 24576 + off);
                ldsm_x2t(vl[j], kb + 36864 + off);
            }
#pragma unroll
            for (int ti = 0; ti < 2; ++ti)
#pragma unroll
                for (int j = 0; j < 6; ++j) {
                    mma16816(acc[ti][j], ph[ti], vh[j]);
                    mma16816(acc[ti][j], ph[ti], vl[j]);
                    mma16816(acc[ti][j], pl[ti], vh[j]);
                }
        }
    }

    // ---- epilogue: normalize, split to bf16 hi/lo, store ----
    float inv[2][2];
#pragma unroll
    for (int ti = 0; ti < 2; ++ti)
#pragma unroll
        for (int hh = 0; hh < 2; ++hh)
            inv[ti][hh] = 1.f / l_run[ti][hh];

#pragma unroll
    for (int ti = 0; ti < 2; ++ti)
#pragma unroll
        for (int j = 0; j < 6; ++j) {
            int col = wn * 48 + j * 8 + (lane & 3) * 2;
            if (col >= HD) continue;
#pragma unroll
            for (int hh = 0; hh < 2; ++hh) {
                int s = q0 + wm * 32 + ti * 16 + hh * 8 + (lane >> 2);
                if (s >= SS) continue;
                float o0 = acc[ti][j][hh * 2] * inv[ti][hh];
                float o1 = acc[ti][j][hh * 2 + 1] * inv[ti][hh];
                uint32_t hi, lo;
                split_pair(o0, o1, hi, lo);
                size_t off = (size_t)(b * SS + s) * KK + (size_t)h * HD + col;
                *(uint32_t*)&attH[off] = hi;
                *(uint32_t*)&attL[off] = lo;
            }
        }
}

// ---------------------------------------------------------------------------
extern "C" void kernel_launch(void* const* d_in, const int* in_sizes, int n_in,
                              void* d_out, int out_size)
{
    const float* hs     = (const float*)d_in[0];
    const float* w_qkv  = (const float*)d_in[1];
    const float* b_qkv  = (const float*)d_in[2];
    const float* w_proj = (const float*)d_in[3];
    const float* b_proj = (const float*)d_in[4];
    float* out = (float*)d_out;

    __nv_bfloat16 *hsH, *hsL, *qkvH, *qkvL, *attH, *attL, *wqH, *wqL, *wpH, *wpL;
    cudaGetSymbolAddress((void**)&hsH, g_hsH);
    cudaGetSymbolAddress((void**)&hsL, g_hsL);
    cudaGetSymbolAddress((void**)&qkvH, g_qkvH);
    cudaGetSymbolAddress((void**)&qkvL, g_qkvL);
    cudaGetSymbolAddress((void**)&attH, g_attH);
    cudaGetSymbolAddress((void**)&attL, g_attL);
    cudaGetSymbolAddress((void**)&wqH, g_wqkvH);
    cudaGetSymbolAddress((void**)&wqL, g_wqkvL);
    cudaGetSymbolAddress((void**)&wpH, g_wprojH);
    cudaGetSymbolAddress((void**)&wpL, g_wprojL);

    const int gemm_smem = STAGES * STAGE_BYTES;   // 96 KB
    cudaFuncSetAttribute(gemm_mma_kernel<0>, cudaFuncAttributeMaxDynamicSharedMemorySize, gemm_smem);
    cudaFuncSetAttribute(gemm_mma_kernel<1>, cudaFuncAttributeMaxDynamicSharedMemorySize, gemm_smem);
    cudaFuncSetAttribute(attn_tc_kernel, cudaFuncAttributeMaxDynamicSharedMemorySize, SM_ATT_TOTAL);

    // 0a) split hidden_states
    {
        int n4 = MM * KK / 4;
        split_kernel<<<(n4 + 255) / 256, 256>>>((const float4*)hs, (uint2*)hsH, (uint2*)hsL, n4);
    }
    // 0b) transpose+split weights
    {
        dim3 g(N1 / 32, KK / 32);
        tsplit_kernel<<<g, dim3(32, 8)>>>(w_qkv, wqH, wqL, KK, N1);
    }
    {
        dim3 g(DD / 32, KK / 32);
        tsplit_kernel<<<g, dim3(32, 8)>>>(w_proj, wpH, wpL, KK, DD);
    }
    // 1) QKV projection -> bf16 hi/lo (q pre-scaled)
    {
        dim3 g(N1 / 128, (MM + 127) / 128);
        gemm_mma_kernel<1><<<g, 256, gemm_smem>>>(hsH, hsL, wqH, wqL, b_qkv,
                                                  nullptr, qkvH, qkvL, MM, N1);
    }
    // 2) tensor-core flash attention -> bf16 hi/lo
    {
        dim3 g((SS + 127) / 128, HH, BB);
        attn_tc_kernel<<<g, 256, SM_ATT_TOTAL>>>(qkvH, qkvL, attH, attL);
    }
    // 3) output projection -> fp32
    {
        dim3 g(DD / 128, (MM + 127) / 128);
        gemm_mma_kernel<0><<<g, 256, gemm_smem>>>(attH, attL, wpH, wpL, b_proj,
                                                  out, nullptr, nullptr, MM, DD);
    }
}